// round 3
// baseline (speedup 1.0000x reference)
#include <cuda_runtime.h>
#include <cstdint>

// Problem constants
#define BATCH   32
#define CDIM    256
#define HWDIM   1024          // H*W = 32*32
#define N_ROWS  32768         // B*H*W
#define KCODES  1024

// Output layout (tuple flattened): [0]=loss, [1..8388608]=quantized(NCHW),
// [8388609]=perplexity, [8388610..]=encodings (32768*1024)
#define QUANT_OFF 1
#define PERP_OFF  8388609
#define ENC_OFF   8388610

// ---------------- scratch (device globals; no allocation) ----------------
__device__ float              g_Xt[N_ROWS * CDIM];   // x transposed to [N, C]
__device__ float              g_xx[N_ROWS];          // ||x_n||^2
__device__ float              g_ee[KCODES];          // ||e_k||^2
__device__ unsigned long long g_rowBest[N_ROWS];     // packed (scoreKey, 1023-idx)
__device__ unsigned int       g_counts[KCODES];
__device__ float              g_kldSum;
__device__ float              g_elatSum;

// ---------------- f32x2 packed helpers ----------------
__device__ __forceinline__ unsigned long long pack2(float lo, float hi) {
    unsigned long long r;
    asm("mov.b64 %0, {%1, %2};" : "=l"(r) : "f"(lo), "f"(hi));
    return r;
}
__device__ __forceinline__ void unpack2(unsigned long long v, float& lo, float& hi) {
    asm("mov.b64 {%0, %1}, %2;" : "=f"(lo), "=f"(hi) : "l"(v));
}
__device__ __forceinline__ unsigned long long fma2(unsigned long long a,
                                                   unsigned long long b,
                                                   unsigned long long c) {
    unsigned long long d;
    asm("fma.rn.f32x2 %0, %1, %2, %3;" : "=l"(d) : "l"(a), "l"(b), "l"(c));
    return d;
}

// ---------------- init ----------------
__global__ void initKernel() {
    int t = blockIdx.x * blockDim.x + threadIdx.x;
    if (t < N_ROWS) g_rowBest[t] = 0ull;
    if (t < KCODES) g_counts[t] = 0u;
    if (t == 0) { g_kldSum = 0.0f; g_elatSum = 0.0f; }
}

// ---------------- NCHW -> [N, C] transpose ----------------
__global__ void transposeKernel(const float* __restrict__ in) {
    __shared__ float tile[32][33];
    int b   = blockIdx.z;
    int hw0 = blockIdx.x << 5;
    int c0  = blockIdx.y << 5;
    const float* p = in + (size_t)b * CDIM * HWDIM;
#pragma unroll
    for (int j = 0; j < 4; j++) {
        int cl = threadIdx.y + (j << 3);
        tile[cl][threadIdx.x] = p[(size_t)(c0 + cl) * HWDIM + hw0 + threadIdx.x];
    }
    __syncthreads();
#pragma unroll
    for (int j = 0; j < 4; j++) {
        int hwl = threadIdx.y + (j << 3);
        g_Xt[(size_t)(b * HWDIM + hw0 + hwl) * CDIM + c0 + threadIdx.x] =
            tile[threadIdx.x][hwl];
    }
}

// ---------------- row sum-of-squares ----------------
__global__ void sumsqXt() {
    int gw   = (blockIdx.x * blockDim.x + threadIdx.x) >> 5;
    int lane = threadIdx.x & 31;
    if (gw >= N_ROWS) return;
    const float* p = g_Xt + (size_t)gw * CDIM;
    float4 a = *(const float4*)(p + (lane << 2));
    float4 b = *(const float4*)(p + 128 + (lane << 2));
    float s = a.x*a.x + a.y*a.y + a.z*a.z + a.w*a.w
            + b.x*b.x + b.y*b.y + b.z*b.z + b.w*b.w;
#pragma unroll
    for (int off = 16; off; off >>= 1) s += __shfl_xor_sync(0xFFFFFFFFu, s, off);
    if (lane == 0) g_xx[gw] = s;
}

__global__ void sumsqE(const float* __restrict__ E) {
    int gw   = (blockIdx.x * blockDim.x + threadIdx.x) >> 5;
    int lane = threadIdx.x & 31;
    if (gw >= KCODES) return;
    const float* p = E + (size_t)gw * CDIM;
    float4 a = *(const float4*)(p + (lane << 2));
    float4 b = *(const float4*)(p + 128 + (lane << 2));
    float s = a.x*a.x + a.y*a.y + a.z*a.z + a.w*a.w
            + b.x*b.x + b.y*b.y + b.z*b.z + b.w*b.w;
#pragma unroll
    for (int off = 16; off; off >>= 1) s += __shfl_xor_sync(0xFFFFFFFFu, s, off);
    if (lane == 0) g_ee[gw] = s;
}

// ---------------- fused score GEMM + argmax + kld + encodings zeros ----------------
// S[n,k] computed as dot(x_n, e_k); d = (xx+ee) - 2*dot; score = gumbel - d.
__global__ __launch_bounds__(256, 2)
void scoreKernel(const float* __restrict__ E, const float* __restrict__ G,
                 float* __restrict__ enc) {
    __shared__ float As[16][128];
    __shared__ float Bs[16][128];

    const int tid = threadIdx.x;
    const int tx  = tid & 15;
    const int ty  = tid >> 4;
    const int m0  = blockIdx.y << 7;   // row (n) tile
    const int j0  = blockIdx.x << 7;   // col (k code) tile

    const float* Ap = g_Xt + (size_t)m0 * CDIM;
    const float* Bp = E    + (size_t)j0 * CDIM;

    unsigned long long acc[8][4];
#pragma unroll
    for (int i = 0; i < 8; i++)
#pragma unroll
        for (int j = 0; j < 4; j++) acc[i][j] = 0ull;

    // prefetch k0 = 0 tile into registers
    float4 ra[2], rb[2];
#pragma unroll
    for (int t = 0; t < 2; t++) {
        int id = tid + (t << 8);
        int r = id >> 2, c4 = id & 3;
        ra[t] = *(const float4*)(Ap + (size_t)r * CDIM + (c4 << 2));
        rb[t] = *(const float4*)(Bp + (size_t)r * CDIM + (c4 << 2));
    }

    for (int k0 = 0; k0 < CDIM; k0 += 16) {
#pragma unroll
        for (int t = 0; t < 2; t++) {
            int id = tid + (t << 8);
            int r = id >> 2, c4 = id & 3;
            As[(c4 << 2) + 0][r] = ra[t].x;
            As[(c4 << 2) + 1][r] = ra[t].y;
            As[(c4 << 2) + 2][r] = ra[t].z;
            As[(c4 << 2) + 3][r] = ra[t].w;
            Bs[(c4 << 2) + 0][r] = rb[t].x;
            Bs[(c4 << 2) + 1][r] = rb[t].y;
            Bs[(c4 << 2) + 2][r] = rb[t].z;
            Bs[(c4 << 2) + 3][r] = rb[t].w;
        }
        __syncthreads();
        if (k0 + 16 < CDIM) {
#pragma unroll
            for (int t = 0; t < 2; t++) {
                int id = tid + (t << 8);
                int r = id >> 2, c4 = id & 3;
                ra[t] = *(const float4*)(Ap + (size_t)r * CDIM + k0 + 16 + (c4 << 2));
                rb[t] = *(const float4*)(Bp + (size_t)r * CDIM + k0 + 16 + (c4 << 2));
            }
        }
#pragma unroll
        for (int kk = 0; kk < 16; kk++) {
            float4 a0 = *(const float4*)&As[kk][ty << 3];
            float4 a1 = *(const float4*)&As[kk][(ty << 3) + 4];
            float4 b0 = *(const float4*)&Bs[kk][tx << 3];
            float4 b1 = *(const float4*)&Bs[kk][(tx << 3) + 4];
            unsigned long long bp[4] = { pack2(b0.x, b0.y), pack2(b0.z, b0.w),
                                         pack2(b1.x, b1.y), pack2(b1.z, b1.w) };
            float av[8] = { a0.x, a0.y, a0.z, a0.w, a1.x, a1.y, a1.z, a1.w };
#pragma unroll
            for (int i = 0; i < 8; i++) {
                unsigned long long ad = pack2(av[i], av[i]);
#pragma unroll
                for (int j = 0; j < 4; j++) acc[i][j] = fma2(ad, bp[j], acc[i][j]);
            }
        }
        __syncthreads();
    }

    // ---------------- epilogue ----------------
    float xv[8], ev[8];
#pragma unroll
    for (int i = 0; i < 8; i++) xv[i] = g_xx[m0 + (ty << 3) + i];
#pragma unroll
    for (int j = 0; j < 8; j++) ev[j] = g_ee[j0 + (tx << 3) + j];

    float kld = 0.0f;
#pragma unroll
    for (int i = 0; i < 8; i++) {
        int mr = m0 + (ty << 3) + i;
        const float* gp = G + (size_t)mr * KCODES + j0 + (tx << 3);
        float4 g0 = *(const float4*)gp;
        float4 g1 = *(const float4*)(gp + 4);
        float gv[8] = { g0.x, g0.y, g0.z, g0.w, g1.x, g1.y, g1.z, g1.w };

        // encodings: zero our 8 entries. NOTE: enc base = out+ENC_OFF is only
        // 8-byte aligned (ENC_OFF % 4 == 2), so use float2, never float4.
        float* ep = enc + (size_t)mr * KCODES + j0 + (tx << 3);
        float2 z2 = make_float2(0.f, 0.f);
        *(float2*)(ep + 0) = z2;
        *(float2*)(ep + 2) = z2;
        *(float2*)(ep + 4) = z2;
        *(float2*)(ep + 6) = z2;

        float accf[8];
        unpack2(acc[i][0], accf[0], accf[1]);
        unpack2(acc[i][1], accf[2], accf[3]);
        unpack2(acc[i][2], accf[4], accf[5]);
        unpack2(acc[i][3], accf[6], accf[7]);

        unsigned long long best = 0ull;
#pragma unroll
        for (int j = 0; j < 8; j++) {
            float d = (xv[i] + ev[j]) - 2.0f * accf[j];   // mirrors (xx+ee) - 2*mat
            float s = gv[j] - d;                           // == -d + g
            if (d < 85.0f) {  // sigmoid(-d) nonzero only here; practically never
                float p = 1.0f / (1.0f + expf(d));
                kld += p * logf(fmaxf(p, 1e-8f));
            }
            unsigned u = __float_as_uint(s);
            u = (u & 0x80000000u) ? ~u : (u | 0x80000000u);   // order-preserving map
            unsigned long long key =
                ((unsigned long long)u << 32) |
                (unsigned)(KCODES - 1 - (j0 + (tx << 3) + j)); // ties -> lowest idx
            best = best > key ? best : key;
        }
        // reduce over the 16 lanes (same ty) covering this row's 128 cols
#pragma unroll
        for (int off = 8; off; off >>= 1) {
            unsigned long long o = __shfl_down_sync(0xFFFFFFFFu, best, off, 16);
            if (o > best) best = o;
        }
        if (tx == 0) atomicMax(&g_rowBest[mr], best);
    }

#pragma unroll
    for (int off = 16; off; off >>= 1) kld += __shfl_down_sync(0xFFFFFFFFu, kld, off);
    if ((tid & 31) == 0 && kld != 0.0f) atomicAdd(&g_kldSum, kld);
}

// ---------------- finish: one-hot scatter, quantized gather+NCHW write,
//                  e_latent partial sums, histogram ----------------
__global__ __launch_bounds__(256)
void finishKernel(const float* __restrict__ E, float* __restrict__ out) {
    __shared__ int   sIdx[32];
    __shared__ float sQ[32 * 257];
    __shared__ float r2[8];

    const int n0  = blockIdx.x << 5;   // 32 rows per CTA
    const int tid = threadIdx.x;

    if (tid < 32) {
        unsigned long long pk = g_rowBest[n0 + tid];
        int idx = (KCODES - 1) - (int)(pk & 0xFFFFFFFFull);
        sIdx[tid] = idx;
        out[ENC_OFF + (size_t)(n0 + tid) * KCODES + idx] = 1.0f;
        atomicAdd(&g_counts[idx], 1u);
    }
    __syncthreads();

    float accum = 0.0f;
    const int c = tid;  // 256 threads == CDIM
#pragma unroll 4
    for (int i = 0; i < 32; i++) {
        float v = E[(size_t)sIdx[i] * CDIM + c];
        float x = g_Xt[(size_t)(n0 + i) * CDIM + c];
        float dlt = v - x;
        accum += dlt * dlt;
        sQ[i * 257 + c] = v;
    }
    __syncthreads();

    // write quantized in NCHW, coalesced: 32 consecutive hw per 32-thread group
    const int b   = n0 >> 10;
    const int hw0 = n0 & 1023;
    float* qb = out + QUANT_OFF + (size_t)b * CDIM * HWDIM;
#pragma unroll 4
    for (int it = 0; it < 32; it++) {
        int f  = it * 256 + tid;
        int cc = f >> 5;
        int ii = f & 31;
        qb[(size_t)cc * HWDIM + hw0 + ii] = sQ[ii * 257 + cc];
    }

    // block-reduce e_latent partial
#pragma unroll
    for (int off = 16; off; off >>= 1) accum += __shfl_down_sync(0xFFFFFFFFu, accum, off);
    if ((tid & 31) == 0) r2[tid >> 5] = accum;
    __syncthreads();
    if (tid == 0) {
        float s = 0.0f;
#pragma unroll
        for (int w = 0; w < 8; w++) s += r2[w];
        atomicAdd(&g_elatSum, s);
    }
}

// ---------------- scalars: loss + perplexity ----------------
__global__ void lossKernel(float* __restrict__ out) {
    __shared__ float red[32];
    int t = threadIdx.x;  // 1024 threads == KCODES
    float avg  = (float)g_counts[t] * (1.0f / 32768.0f);
    float term = avg * logf(avg + 1e-10f);
#pragma unroll
    for (int off = 16; off; off >>= 1) term += __shfl_down_sync(0xFFFFFFFFu, term, off);
    if ((t & 31) == 0) red[t >> 5] = term;
    __syncthreads();
    if (t < 32) {
        float v = red[t];
#pragma unroll
        for (int off = 16; off; off >>= 1) v += __shfl_down_sync(0xFFFFFFFFu, v, off);
        if (t == 0) {
            float perp = expf(-v);
            float eLat = g_elatSum * (1.0f / 8388608.0f);
            float kld  = g_kldSum * (1.0f / 32768.0f);
            float loss = 1.5f * (kld + eLat * (kld / fmaxf(eLat, 1e-8f)));
            out[0]        = loss;
            out[PERP_OFF] = perp;
        }
    }
}

// ---------------- launch ----------------
extern "C" void kernel_launch(void* const* d_in, const int* in_sizes, int n_in,
                              void* d_out, int out_size) {
    const float* inp = (const float*)d_in[0];   // [32,256,32,32]
    const float* emb = (const float*)d_in[1];   // [1024,256]
    const float* gum = (const float*)d_in[2];   // [32768,1024]
    float* out = (float*)d_out;
    float* enc = out + ENC_OFF;

    initKernel<<<128, 256>>>();
    transposeKernel<<<dim3(32, 8, 32), dim3(32, 8)>>>(inp);
    sumsqXt<<<4096, 256>>>();
    sumsqE<<<128, 256>>>(emb);
    scoreKernel<<<dim3(KCODES / 128, N_ROWS / 128), 256>>>(emb, gum, enc);
    finishKernel<<<N_ROWS / 32, 256>>>(emb, out);
    lossKernel<<<1, 1024>>>(out);
}